// round 5
// baseline (speedup 1.0000x reference)
#include <cuda_runtime.h>
#include <cstdint>
#include <cstddef>

// Problem shape (fixed by dataset: B=2048, S=2048, H=64)
#define BB 2048
#define SS 2048
#define HH 64
#define EPSV 1e-6f
#define FULLMASK 0xFFFFFFFFu

typedef unsigned long long ull;

__device__ __forceinline__ ull fma2(ull a, ull b, ull c) {
    ull d;
    asm("fma.rn.f32x2 %0, %1, %2, %3;" : "=l"(d) : "l"(a), "l"(b), "l"(c));
    return d;
}
__device__ __forceinline__ ull add2(ull a, ull b) {
    ull d;
    asm("add.rn.f32x2 %0, %1, %2;" : "=l"(d) : "l"(a), "l"(b));
    return d;
}
__device__ __forceinline__ float2 unpack2(ull a) {
    float2 r;
    asm("mov.b64 {%0, %1}, %2;" : "=f"(r.x), "=f"(r.y) : "l"(a));
    return r;
}
__device__ __forceinline__ ull pack2(float x, float y) {
    ull r;
    asm("mov.b64 %0, {%1, %2};" : "=l"(r) : "f"(x), "f"(y));
    return r;
}
// softplus(x) = max(x,0) + log1p(exp(-|x|)), fast MUFU path with log1p correction
__device__ __forceinline__ float softplus_fast(float x) {
    float t = __expf(-fabsf(x));
    float u = 1.f + t;
    float lg = __logf(u) + __fdividef(t - (u - 1.f), u);
    return fmaxf(x, 0.f) + lg;
}

// sigma0 scratch
__device__ float g_sig0[BB];

// --------------------------------------------------------------------------
// Kernel 1: unbiased variance per row -> g_sig0[b] and out[b*S + 0]
// --------------------------------------------------------------------------
__global__ void __launch_bounds__(256) var_kernel(const float* __restrict__ res,
                                                  float* __restrict__ out) {
    int b = blockIdx.x;
    const float* row = res + (size_t)b * SS;
    float s = 0.f, s2 = 0.f;
    for (int i = threadIdx.x; i < SS; i += 256) {
        float v = row[i];
        s += v;
        s2 = fmaf(v, v, s2);
    }
#pragma unroll
    for (int o = 16; o; o >>= 1) {
        s  += __shfl_xor_sync(FULLMASK, s,  o);
        s2 += __shfl_xor_sync(FULLMASK, s2, o);
    }
    __shared__ float sh[16];
    int w = threadIdx.x >> 5, l = threadIdx.x & 31;
    if (l == 0) { sh[w] = s; sh[w + 8] = s2; }
    __syncthreads();
    if (threadIdx.x == 0) {
        float S1 = 0.f, S2 = 0.f;
#pragma unroll
        for (int i = 0; i < 8; i++) { S1 += sh[i]; S2 += sh[i + 8]; }
        float var = (S2 - S1 * S1 / (float)SS) / (float)(SS - 1);
        g_sig0[b] = var;
        out[(size_t)b * SS] = var;
    }
}

// --------------------------------------------------------------------------
// Kernel 2: recurrence. ONE 32-thread block = ONE batch row; 2048 blocks at
// 14 blocks/SM -> ALL batches resident in a single wave (no 2x wave tail).
// W_hh rows in registers (f32x2-packed). All other per-step constants live
// in per-warp shared memory to fit the 144-reg budget.
// --------------------------------------------------------------------------
__global__ void __launch_bounds__(32, 14) rnn_kernel(
    const float* __restrict__ res,   // [B][S]
    const float* __restrict__ Wih,   // [64][2]
    const float* __restrict__ bih,   // [64]
    const float* __restrict__ Whh,   // [64][64]
    const float* __restrict__ bhh,   // [64]
    const float* __restrict__ fcw,   // [64]
    const float* __restrict__ fcb1,  // [1]
    float* __restrict__ out)         // [B][S]
{
    const int lane = threadIdx.x;
    const int b    = blockIdx.x;
    const int r0   = lane, r1 = lane + 32;

    // W_hh rows for this lane, packed f32x2 along k (128 regs)
    ull w0[32], w1[32];
    {
        const ull* p0v = (const ull*)(Whh + r0 * HH);
        const ull* p1v = (const ull*)(Whh + r1 * HH);
#pragma unroll
        for (int i = 0; i < 32; i++) { w0[i] = p0v[i]; w1[i] = p1v[i]; }
    }

    // Per-warp shared: h ping-pong + spilled per-step constants
    __shared__ __align__(16) float hb[2][HH];
    __shared__ ull  ush[32];   // (u0,u1) per lane:  u = fc^T W_hh columns
    __shared__ ull  wps0[32];  // (wih00, wih01) per lane
    __shared__ ull  wps1[32];  // (wih10, wih11) per lane
    __shared__ ull  bbs[32];   // (bb0, bb1) per lane
    __shared__ ull  pps;       // (p1s, p2s)
    __shared__ float cs;       // c

    {
        // u (per-lane) and warp-uniform p1,p2,c
        float u0 = 0.f, u1 = 0.f, p1 = 0.f, p2 = 0.f, c = fcb1[0];
#pragma unroll 4
        for (int j = 0; j < HH; j++) {
            float f = fcw[j];
            u0 = fmaf(f, Whh[j * HH + r0], u0);
            u1 = fmaf(f, Whh[j * HH + r1], u1);
            p1 = fmaf(f, Wih[2 * j],     p1);
            p2 = fmaf(f, Wih[2 * j + 1], p2);
            c  = fmaf(f, bih[j] + bhh[j], c);
        }
        ush[lane]  = pack2(u0, u1);
        wps0[lane] = ((const ull*)Wih)[r0];
        wps1[lane] = ((const ull*)Wih)[r1];
        bbs[lane]  = pack2(bih[r0] + bhh[r0], bih[r1] + bhh[r1]);
        if (lane == 0) { pps = pack2(p1, p2); cs = c; }
        hb[0][r0] = 0.f;
        hb[0][r1] = 0.f;
    }
    __syncwarp();

    float sig = g_sig0[b];
    const float* rp = res + (size_t)b * SS;           // points at eps index t-1
    const ptrdiff_t ddiff = (const char*)out - (const char*)res;  // uniform

    float e  = rp[0];
    float h0 = 0.f, h1 = 0.f;   // this lane's rows of h_{t-1} (registers)

#define STEP(PSRC, PDST)                                                     \
    {                                                                        \
        const float e2 = e * e;                                              \
        e = rp[1];                                                           \
        /* sigma dot on register h (off h->h critical path) */               \
        float2 uv = unpack2(ush[lane]);                                      \
        float d = fmaf(uv.x, h0, uv.y * h1);                                 \
        _Pragma("unroll")                                                    \
        for (int o = 16; o; o >>= 1) d += __shfl_xor_sync(FULLMASK, d, o);   \
        /* matvec from shared h_{t-1}: 4 independent f32x2 chains */         \
        const float* h = hb[PSRC];                                           \
        ull x0 = 0ull, y0 = 0ull, x1 = 0ull, y1 = 0ull;                      \
        _Pragma("unroll")                                                    \
        for (int i = 0; i < 16; i++) {                                       \
            ulonglong2 hv = *(const ulonglong2*)(h + 4 * i);                 \
            x0 = fma2(w0[2 * i],     hv.x, x0);                              \
            y0 = fma2(w0[2 * i + 1], hv.y, y0);                              \
            x1 = fma2(w1[2 * i],     hv.x, x1);                              \
            y1 = fma2(w1[2 * i + 1], hv.y, y1);                              \
        }                                                                    \
        /* sigma */                                                          \
        float2 pp = unpack2(pps);                                            \
        float xs = d + fmaf(pp.x, e2, fmaf(pp.y, sig, cs));                  \
        float ns = softplus_fast(xs) + EPSV;                                 \
        /* combine h (uses OLD sigma) */                                     \
        ull es = pack2(e2, sig);                                             \
        float2 q0 = unpack2(fma2(es, wps0[lane], 0ull));                     \
        float2 q1 = unpack2(fma2(es, wps1[lane], 0ull));                     \
        float2 bbv = unpack2(bbs[lane]);                                     \
        float2 v;                                                            \
        v = unpack2(add2(x0, y0));                                           \
        h0 = (v.x + v.y) + (q0.x + q0.y + bbv.x);                            \
        v = unpack2(add2(x1, y1));                                           \
        h1 = (v.x + v.y) + (q1.x + q1.y + bbv.y);                            \
        /* publish */                                                        \
        hb[PDST][r0] = h0;                                                   \
        hb[PDST][r1] = h1;                                                   \
        __syncwarp();                                                        \
        sig = ns;                                                            \
        if (lane == 0) *(float*)((char*)(rp + 1) + ddiff) = ns;              \
        rp++;                                                                \
    }

    // peel t=1 (buf0 -> buf1), then 1023 unrolled pairs (1 + 2046 = 2047)
    STEP(0, 1)
#pragma unroll 1
    for (int it = 0; it < (SS - 2) / 2; ++it) {
        STEP(1, 0)
        STEP(0, 1)
    }
#undef STEP
}

// --------------------------------------------------------------------------
extern "C" void kernel_launch(void* const* d_in, const int* in_sizes, int n_in,
                              void* d_out, int out_size) {
    const float* res  = (const float*)d_in[0];
    const float* Wih  = (const float*)d_in[1];
    const float* bih  = (const float*)d_in[2];
    const float* Whh  = (const float*)d_in[3];
    const float* bhh  = (const float*)d_in[4];
    const float* fcw  = (const float*)d_in[5];
    const float* fcb  = (const float*)d_in[6];
    float* out = (float*)d_out;

    var_kernel<<<BB, 256>>>(res, out);
    rnn_kernel<<<BB, 32>>>(res, Wih, bih, Whh, bhh, fcw, fcb, out);
}

// round 6
// speedup vs baseline: 1.7195x; 1.7195x over previous
#include <cuda_runtime.h>
#include <cstdint>
#include <cstddef>

// Problem shape (fixed by dataset: B=2048, S=2048, H=64)
#define BB 2048
#define SS 2048
#define HH 64
#define EPSV 1e-6f
#define FULLMASK 0xFFFFFFFFu

typedef unsigned long long ull;

__device__ __forceinline__ ull fma2(ull a, ull b, ull c) {
    ull d;
    asm("fma.rn.f32x2 %0, %1, %2, %3;" : "=l"(d) : "l"(a), "l"(b), "l"(c));
    return d;
}
__device__ __forceinline__ ull add2(ull a, ull b) {
    ull d;
    asm("add.rn.f32x2 %0, %1, %2;" : "=l"(d) : "l"(a), "l"(b));
    return d;
}
__device__ __forceinline__ float2 unpack2(ull a) {
    float2 r;
    asm("mov.b64 {%0, %1}, %2;" : "=f"(r.x), "=f"(r.y) : "l"(a));
    return r;
}
// softplus(x) = max(x,0) + log1p(exp(-|x|)), fast MUFU path with log1p correction
__device__ __forceinline__ float softplus_fast(float x) {
    float t = __expf(-fabsf(x));
    float u = 1.f + t;
    float lg = __logf(u) + __fdividef(t - (u - 1.f), u);
    return fmaxf(x, 0.f) + lg;
}

// sigma0 scratch
__device__ float g_sig0[BB];

// --------------------------------------------------------------------------
// Kernel 1: unbiased variance per row -> g_sig0[b] and out[b*S + 0]
// --------------------------------------------------------------------------
__global__ void __launch_bounds__(256) var_kernel(const float* __restrict__ res,
                                                  float* __restrict__ out) {
    int b = blockIdx.x;
    const float* row = res + (size_t)b * SS;
    float s = 0.f, s2 = 0.f;
    for (int i = threadIdx.x; i < SS; i += 256) {
        float v = row[i];
        s += v;
        s2 = fmaf(v, v, s2);
    }
#pragma unroll
    for (int o = 16; o; o >>= 1) {
        s  += __shfl_xor_sync(FULLMASK, s,  o);
        s2 += __shfl_xor_sync(FULLMASK, s2, o);
    }
    __shared__ float sh[16];
    int w = threadIdx.x >> 5, l = threadIdx.x & 31;
    if (l == 0) { sh[w] = s; sh[w + 8] = s2; }
    __syncthreads();
    if (threadIdx.x == 0) {
        float S1 = 0.f, S2 = 0.f;
#pragma unroll
        for (int i = 0; i < 8; i++) { S1 += sh[i]; S2 += sh[i + 8]; }
        float var = (S2 - S1 * S1 / (float)SS) / (float)(SS - 1);
        g_sig0[b] = var;
        out[(size_t)b * SS] = var;
    }
}

// --------------------------------------------------------------------------
// Kernel 2: recurrence. ONE 64-thread block = ONE batch row; each thread owns
// ONE h row (64 weight regs/lane -> no spills, 9 blocks/SM residency).
// h and the sigma partial dots ping-pong in shared; one __syncthreads per
// step. sigma path: fc.h_t = u.h_{t-1} + p1*eps^2 + p2*sigma + c with
// u = fc^T W_hh precomputed -> sigma dot on REGISTER h, off the critical path.
// --------------------------------------------------------------------------
__global__ void __launch_bounds__(64, 9) rnn_kernel(
    const float* __restrict__ res,   // [B][S]
    const float* __restrict__ Wih,   // [64][2]
    const float* __restrict__ bih,   // [64]
    const float* __restrict__ Whh,   // [64][64]
    const float* __restrict__ bhh,   // [64]
    const float* __restrict__ fcw,   // [64]
    const float* __restrict__ fcb1,  // [1]
    float* __restrict__ out)         // [B][S]
{
    const int tid  = threadIdx.x;        // 0..63 == owned h row
    const int w    = tid >> 5;           // warp id in block (0/1)
    const int b    = blockIdx.x;

    // W_hh row for this thread, packed f32x2 along k (64 regs)
    ull wreg[32];
    {
        const ull* pv = (const ull*)(Whh + tid * HH);
#pragma unroll
        for (int i = 0; i < 32; i++) wreg[i] = pv[i];
    }
    const float wih0 = Wih[tid * 2], wih1 = Wih[tid * 2 + 1];
    const float bb   = bih[tid] + bhh[tid];

    // u[tid] = (fc^T W_hh)[tid]  (column dot; coalesced), p1/p2/c uniform
    float ur = 0.f, p1s = 0.f, p2s = 0.f, c = fcb1[0];
#pragma unroll 4
    for (int j = 0; j < HH; j++) {
        float f = fcw[j];
        ur  = fmaf(f, Whh[j * HH + tid], ur);
        p1s = fmaf(f, Wih[2 * j],     p1s);
        p2s = fmaf(f, Wih[2 * j + 1], p2s);
        c   = fmaf(f, bih[j] + bhh[j], c);
    }

    // ping-pong h + ping-pong per-warp sigma partials
    __shared__ __align__(16) float hb[2][HH];
    __shared__ float dp[2][2];

    hb[0][tid] = 0.f;
    if (tid < 2) { dp[0][tid] = 0.f; dp[1][tid] = 0.f; }
    __syncthreads();

    float sig = g_sig0[b];
    const float* rp = res + (size_t)b * SS;   // rp[0] is eps_{t-1} at step t
    float* op = out + (size_t)b * SS;

    float e  = rp[0];
    float hr = 0.f;                            // own row of h_{t-1}

#define STEP(PSRC, PDST)                                                      \
    {                                                                         \
        const float e2 = e * e;                                               \
        e = rp[1];                                                            \
        /* sigma partial dot on register h (own row), butterfly in-warp */    \
        float d = ur * hr;                                                    \
        _Pragma("unroll")                                                     \
        for (int o = 16; o; o >>= 1) d += __shfl_xor_sync(FULLMASK, d, o);    \
        if ((tid & 31) == 0) dp[PDST][w] = d;                                 \
        /* matvec row: 2 independent f32x2 chains over shared h_{t-1} */      \
        const float* h = hb[PSRC];                                            \
        ull x = 0ull, y = 0ull;                                               \
        _Pragma("unroll")                                                     \
        for (int i = 0; i < 16; i++) {                                        \
            ulonglong2 hv = *(const ulonglong2*)(h + 4 * i);                  \
            x = fma2(wreg[2 * i],     hv.x, x);                               \
            y = fma2(wreg[2 * i + 1], hv.y, y);                               \
        }                                                                     \
        float2 v = unpack2(add2(x, y));                                       \
        hr = (v.x + v.y) + fmaf(e2, wih0, fmaf(sig, wih1, bb));               \
        hb[PDST][tid] = hr;                                                   \
        __syncthreads();                                                      \
        /* sigma update (both warps redundantly; uniform) */                  \
        float ds = dp[PDST][0] + dp[PDST][1];                                 \
        float xs = ds + fmaf(p1s, e2, fmaf(p2s, sig, c));                     \
        sig = softplus_fast(xs) + EPSV;                                       \
        if (tid == 0) op[1] = sig;                                            \
        rp++; op++;                                                           \
    }

    // t=1 peeled (buf0 -> buf1), then 1023 unrolled pairs (1 + 2046 = 2047)
    STEP(0, 1)
#pragma unroll 1
    for (int it = 0; it < (SS - 2) / 2; ++it) {
        STEP(1, 0)
        STEP(0, 1)
    }
#undef STEP
}

// --------------------------------------------------------------------------
extern "C" void kernel_launch(void* const* d_in, const int* in_sizes, int n_in,
                              void* d_out, int out_size) {
    const float* res  = (const float*)d_in[0];
    const float* Wih  = (const float*)d_in[1];
    const float* bih  = (const float*)d_in[2];
    const float* Whh  = (const float*)d_in[3];
    const float* bhh  = (const float*)d_in[4];
    const float* fcw  = (const float*)d_in[5];
    const float* fcb  = (const float*)d_in[6];
    float* out = (float*)d_out;

    var_kernel<<<BB, 256>>>(res, out);
    rnn_kernel<<<BB, 64>>>(res, Wih, bih, Whh, bhh, fcw, fcb, out);
}

// round 8
// speedup vs baseline: 1.8461x; 1.0737x over previous
#include <cuda_runtime.h>
#include <cstdint>
#include <cstddef>

// Problem shape (fixed by dataset: B=2048, S=2048, H=64)
#define BB 2048
#define SS 2048
#define HH 64
#define EPSV 1e-6f
#define FULLMASK 0xFFFFFFFFu

typedef unsigned long long ull;

__device__ __forceinline__ ull fma2(ull a, ull b, ull c) {
    ull d;
    asm("fma.rn.f32x2 %0, %1, %2, %3;" : "=l"(d) : "l"(a), "l"(b), "l"(c));
    return d;
}
__device__ __forceinline__ ull add2(ull a, ull b) {
    ull d;
    asm("add.rn.f32x2 %0, %1, %2;" : "=l"(d) : "l"(a), "l"(b));
    return d;
}
__device__ __forceinline__ float2 unpack2(ull a) {
    float2 r;
    asm("mov.b64 {%0, %1}, %2;" : "=f"(r.x), "=f"(r.y) : "l"(a));
    return r;
}
// softplus(x) = max(x,0) + log1p(exp(-|x|)), fast MUFU path with log1p correction
__device__ __forceinline__ float softplus_fast(float x) {
    float t = __expf(-fabsf(x));
    float u = 1.f + t;
    float lg = __logf(u) + __fdividef(t - (u - 1.f), u);
    return fmaxf(x, 0.f) + lg;
}

// sigma0 scratch
__device__ float g_sig0[BB];

// --------------------------------------------------------------------------
// Kernel 1: unbiased variance per row -> g_sig0[b] and out[b*S + 0]
// --------------------------------------------------------------------------
__global__ void __launch_bounds__(256) var_kernel(const float* __restrict__ res,
                                                  float* __restrict__ out) {
    int b = blockIdx.x;
    const float* row = res + (size_t)b * SS;
    float s = 0.f, s2 = 0.f;
    for (int i = threadIdx.x; i < SS; i += 256) {
        float v = row[i];
        s += v;
        s2 = fmaf(v, v, s2);
    }
#pragma unroll
    for (int o = 16; o; o >>= 1) {
        s  += __shfl_xor_sync(FULLMASK, s,  o);
        s2 += __shfl_xor_sync(FULLMASK, s2, o);
    }
    __shared__ float sh[16];
    int w = threadIdx.x >> 5, l = threadIdx.x & 31;
    if (l == 0) { sh[w] = s; sh[w + 8] = s2; }
    __syncthreads();
    if (threadIdx.x == 0) {
        float S1 = 0.f, S2 = 0.f;
#pragma unroll
        for (int i = 0; i < 8; i++) { S1 += sh[i]; S2 += sh[i + 8]; }
        float var = (S2 - S1 * S1 / (float)SS) / (float)(SS - 1);
        g_sig0[b] = var;
        out[(size_t)b * SS] = var;
    }
}

// --------------------------------------------------------------------------
// Kernel 2: recurrence. ONE 64-thread block = TWO batch rows (weights are
// shared between batches: each thread owns one h row -> same 64 weight regs
// serve both). grid = 1024 blocks <= 148*7 -> ALL batches resident, single
// wave. The two independent batch chains interleave inside each warp and
// hide the dependency/bar latency that stalled the 1-batch version.
// --------------------------------------------------------------------------
__global__ void __launch_bounds__(64, 7) rnn_kernel(
    const float* __restrict__ res,   // [B][S]
    const float* __restrict__ Wih,   // [64][2]
    const float* __restrict__ bih,   // [64]
    const float* __restrict__ Whh,   // [64][64]
    const float* __restrict__ bhh,   // [64]
    const float* __restrict__ fcw,   // [64]
    const float* __restrict__ fcb1,  // [1]
    float* __restrict__ out)         // [B][S]
{
    const int tid = threadIdx.x;         // 0..63 == owned h row
    const int w   = tid >> 5;            // warp in block (0/1)
    const int b0  = blockIdx.x * 2;      // batches b0, b0+1

    // W_hh row for this thread, packed f32x2 along k (64 regs, batch-shared)
    ull wreg[32];
    {
        const ull* pv = (const ull*)(Whh + tid * HH);
#pragma unroll
        for (int i = 0; i < 32; i++) wreg[i] = pv[i];
    }
    const float wih0 = Wih[tid * 2], wih1 = Wih[tid * 2 + 1];
    const float bb   = bih[tid] + bhh[tid];

    // u[tid] = (fc^T W_hh)[tid] (coalesced column dot), p1/p2/c uniform
    float ur = 0.f, p1s = 0.f, p2s = 0.f, c = fcb1[0];
#pragma unroll 4
    for (int j = 0; j < HH; j++) {
        float f = fcw[j];
        ur  = fmaf(f, Whh[j * HH + tid], ur);
        p1s = fmaf(f, Wih[2 * j],     p1s);
        p2s = fmaf(f, Wih[2 * j + 1], p2s);
        c   = fmaf(f, bih[j] + bhh[j], c);
    }

    // ping-pong h per batch + ping-pong per-warp sigma partials per batch
    __shared__ __align__(16) float hb[2][2][HH];  // [parity][batch][row]
    __shared__ float dp[2][2][2];                 // [parity][batch][warp]

    hb[0][0][tid] = 0.f;
    hb[0][1][tid] = 0.f;
    if (tid < 4) { dp[0][tid >> 1][tid & 1] = 0.f; dp[1][tid >> 1][tid & 1] = 0.f; }
    __syncthreads();

    float sigA = g_sig0[b0];
    float sigB = g_sig0[b0 + 1];
    const float* rpA = res + (size_t)b0 * SS;   // rp[0] = eps_{t-1} at step t
    const float* rpB = rpA + SS;
    float* opA = out + (size_t)b0 * SS;
    float* opB = opA + SS;

    float eA = rpA[0], eB = rpB[0];
    float hrA = 0.f, hrB = 0.f;                 // own rows of h_{t-1}

#define STEP(PSRC, PDST)                                                       \
    {                                                                          \
        const float e2A = eA * eA, e2B = eB * eB;                              \
        eA = rpA[1]; eB = rpB[1];                                              \
        /* sigma partial dots on register h (own rows); 2 indep butterflies */ \
        float dA = ur * hrA, dB = ur * hrB;                                    \
        _Pragma("unroll")                                                      \
        for (int o = 16; o; o >>= 1) {                                         \
            dA += __shfl_xor_sync(FULLMASK, dA, o);                            \
            dB += __shfl_xor_sync(FULLMASK, dB, o);                            \
        }                                                                      \
        if ((tid & 31) == 0) { dp[PDST][0][w] = dA; dp[PDST][1][w] = dB; }     \
        /* matvec rows: 4 independent f32x2 chains over both shared h's */     \
        const float* hA = hb[PSRC][0];                                         \
        const float* hB = hb[PSRC][1];                                         \
        ull xA = 0ull, yA = 0ull, xB = 0ull, yB = 0ull;                        \
        _Pragma("unroll")                                                      \
        for (int i = 0; i < 16; i++) {                                         \
            ulonglong2 hvA = *(const ulonglong2*)(hA + 4 * i);                 \
            ulonglong2 hvB = *(const ulonglong2*)(hB + 4 * i);                 \
            xA = fma2(wreg[2 * i],     hvA.x, xA);                             \
            yA = fma2(wreg[2 * i + 1], hvA.y, yA);                             \
            xB = fma2(wreg[2 * i],     hvB.x, xB);                             \
            yB = fma2(wreg[2 * i + 1], hvB.y, yB);                             \
        }                                                                      \
        float2 v;                                                              \
        v = unpack2(add2(xA, yA));                                             \
        hrA = (v.x + v.y) + fmaf(e2A, wih0, fmaf(sigA, wih1, bb));             \
        v = unpack2(add2(xB, yB));                                             \
        hrB = (v.x + v.y) + fmaf(e2B, wih0, fmaf(sigB, wih1, bb));             \
        hb[PDST][0][tid] = hrA;                                                \
        hb[PDST][1][tid] = hrB;                                                \
        __syncthreads();                                                       \
        /* sigma updates (uniform within block) */                             \
        float dsA = dp[PDST][0][0] + dp[PDST][0][1];                           \
        float dsB = dp[PDST][1][0] + dp[PDST][1][1];                           \
        float xsA = dsA + fmaf(p1s, e2A, fmaf(p2s, sigA, c));                  \
        float xsB = dsB + fmaf(p1s, e2B, fmaf(p2s, sigB, c));                  \
        sigA = softplus_fast(xsA) + EPSV;                                      \
        sigB = softplus_fast(xsB) + EPSV;                                      \
        if (tid == 0)  opA[1] = sigA;                                          \
        if (tid == 32) opB[1] = sigB;                                          \
        rpA++; rpB++; opA++; opB++;                                            \
    }

    // t=1 peeled (parity 0 -> 1), then 1023 unrolled pairs (1 + 2046 = 2047)
    STEP(0, 1)
#pragma unroll 1
    for (int it = 0; it < (SS - 2) / 2; ++it) {
        STEP(1, 0)
        STEP(0, 1)
    }
#undef STEP
}

// --------------------------------------------------------------------------
extern "C" void kernel_launch(void* const* d_in, const int* in_sizes, int n_in,
                              void* d_out, int out_size) {
    const float* res  = (const float*)d_in[0];
    const float* Wih  = (const float*)d_in[1];
    const float* bih  = (const float*)d_in[2];
    const float* Whh  = (const float*)d_in[3];
    const float* bhh  = (const float*)d_in[4];
    const float* fcw  = (const float*)d_in[5];
    const float* fcb  = (const float*)d_in[6];
    float* out = (float*)d_out;

    var_kernel<<<BB, 256>>>(res, out);
    rnn_kernel<<<BB / 2, 64>>>(res, Wih, bih, Whh, bhh, fcw, fcb, out);
}

// round 10
// speedup vs baseline: 2.0979x; 1.1364x over previous
#include <cuda_runtime.h>
#include <cstdint>
#include <cstddef>

// Problem shape (fixed by dataset: B=2048, S=2048, H=64)
#define BB 2048
#define SS 2048
#define HH 64
#define EPSV 1e-6f
#define FULLMASK 0xFFFFFFFFu

typedef unsigned long long ull;

__device__ __forceinline__ ull fma2(ull a, ull b, ull c) {
    ull d;
    asm("fma.rn.f32x2 %0, %1, %2, %3;" : "=l"(d) : "l"(a), "l"(b), "l"(c));
    return d;
}
__device__ __forceinline__ ull add2(ull a, ull b) {
    ull d;
    asm("add.rn.f32x2 %0, %1, %2;" : "=l"(d) : "l"(a), "l"(b));
    return d;
}
__device__ __forceinline__ float2 unpack2(ull a) {
    float2 r;
    asm("mov.b64 {%0, %1}, %2;" : "=f"(r.x), "=f"(r.y) : "l"(a));
    return r;
}
__device__ __forceinline__ ull pack2(float x, float y) {
    ull r;
    asm("mov.b64 %0, {%1, %2};" : "=l"(r) : "f"(x), "f"(y));
    return r;
}
// softplus(x) = max(x,0) + log1p(exp(-|x|)), fast MUFU path with log1p correction
__device__ __forceinline__ float softplus_fast(float x) {
    float t = __expf(-fabsf(x));
    float u = 1.f + t;
    float lg = __logf(u) + __fdividef(t - (u - 1.f), u);
    return fmaxf(x, 0.f) + lg;
}

// sigma0 scratch
__device__ float g_sig0[BB];

// --------------------------------------------------------------------------
// Kernel 1: unbiased variance per row -> g_sig0[b] and out[b*S + 0]
// --------------------------------------------------------------------------
__global__ void __launch_bounds__(256) var_kernel(const float* __restrict__ res,
                                                  float* __restrict__ out) {
    int b = blockIdx.x;
    const float* row = res + (size_t)b * SS;
    float s = 0.f, s2 = 0.f;
    for (int i = threadIdx.x; i < SS; i += 256) {
        float v = row[i];
        s += v;
        s2 = fmaf(v, v, s2);
    }
#pragma unroll
    for (int o = 16; o; o >>= 1) {
        s  += __shfl_xor_sync(FULLMASK, s,  o);
        s2 += __shfl_xor_sync(FULLMASK, s2, o);
    }
    __shared__ float sh[16];
    int w = threadIdx.x >> 5, l = threadIdx.x & 31;
    if (l == 0) { sh[w] = s; sh[w + 8] = s2; }
    __syncthreads();
    if (threadIdx.x == 0) {
        float S1 = 0.f, S2 = 0.f;
#pragma unroll
        for (int i = 0; i < 8; i++) { S1 += sh[i]; S2 += sh[i + 8]; }
        float var = (S2 - S1 * S1 / (float)SS) / (float)(SS - 1);
        g_sig0[b] = var;
        out[(size_t)b * SS] = var;
    }
}

// --------------------------------------------------------------------------
// Kernel 2: recurrence, split-K layout. Block = 64 threads = 2 batches.
// Thread (w,l) owns rows l and l+32 over k-half [32w, 32w+32): 64 weight
// regs/thread. Each warp reads only ITS k-half of each batch's h (8 LDS.128
// per batch). Partial row sums exchanged via shared pex; after bar1, warp w
// combines ONLY batch (2*blk + w): input terms, h publish, one butterfly,
// one softplus. 1024 blocks at 8/SM residency -> single wave, all resident.
// --------------------------------------------------------------------------
__global__ void __launch_bounds__(64, 8) rnn_kernel(
    const float* __restrict__ res,   // [B][S]
    const float* __restrict__ Wih,   // [64][2]
    const float* __restrict__ bih,   // [64]
    const float* __restrict__ Whh,   // [64][64]
    const float* __restrict__ bhh,   // [64]
    const float* __restrict__ fcw,   // [64]
    const float* __restrict__ fcb1,  // [1]
    float* __restrict__ out)         // [B][S]
{
    const int tid = threadIdx.x;
    const int w   = tid >> 5;            // warp id = k-half = owned batch
    const int l   = tid & 31;

    // Weights: rows l and l+32, k in [32w, 32w+32), f32x2-packed (64 regs)
    ull wl[16], wh[16];
    {
        const ull* pL = (const ull*)(Whh + l * HH + 32 * w);
        const ull* pH = (const ull*)(Whh + (l + 32) * HH + 32 * w);
#pragma unroll
        for (int i = 0; i < 16; i++) { wl[i] = pL[i]; wh[i] = pH[i]; }
    }
    // Per-row constants for rows l and l+32
    const float wih0L = Wih[l * 2],        wih1L = Wih[l * 2 + 1];
    const float wih0H = Wih[(l + 32) * 2], wih1H = Wih[(l + 32) * 2 + 1];
    const float bbL = bih[l] + bhh[l];
    const float bbH = bih[l + 32] + bhh[l + 32];
    const float fcL = fcw[l], fcH = fcw[l + 32];
    const float fcb = fcb1[0];

    // h per batch + partial-sum exchange (no ping-pong needed: bar-separated)
    __shared__ __align__(16) float hb[2][HH];   // [batch][row]
    __shared__ ull pex[2][2][32];               // [batch][khalf][l]=(sumL,sumH)

    hb[0][tid] = 0.f;
    hb[1][tid] = 0.f;
    __syncthreads();

    const int b = blockIdx.x * 2 + w;           // owned batch
    float sig = g_sig0[b];
    const float* rp = res + (size_t)b * SS;
    float* op = out + (size_t)b * SS;

    float e = rp[0];
    const float* h0w = hb[0] + 32 * w;          // own k-half, batch 0
    const float* h1w = hb[1] + 32 * w;          // own k-half, batch 1

#pragma unroll 1
    for (int t = 1; t < SS; ++t) {
        const float e2 = e * e;
        e = rp[t];   // prefetch next eps (own batch); last value unused

        // ---- partial matvec over own k-half, BOTH batches ----
        ull aL0A = 0ull, aL1A = 0ull, aH0A = 0ull, aH1A = 0ull;
        ull aL0B = 0ull, aL1B = 0ull, aH0B = 0ull, aH1B = 0ull;
#pragma unroll
        for (int i = 0; i < 8; i++) {
            ulonglong2 vA = *(const ulonglong2*)(h0w + 4 * i);   // LDS.128
            ulonglong2 vB = *(const ulonglong2*)(h1w + 4 * i);
            aL0A = fma2(wl[2 * i],     vA.x, aL0A);
            aL1A = fma2(wl[2 * i + 1], vA.y, aL1A);
            aH0A = fma2(wh[2 * i],     vA.x, aH0A);
            aH1A = fma2(wh[2 * i + 1], vA.y, aH1A);
            aL0B = fma2(wl[2 * i],     vB.x, aL0B);
            aL1B = fma2(wl[2 * i + 1], vB.y, aL1B);
            aH0B = fma2(wh[2 * i],     vB.x, aH0B);
            aH1B = fma2(wh[2 * i + 1], vB.y, aH1B);
        }
        float2 vv;
        vv = unpack2(add2(aL0A, aL1A)); const float sLA = vv.x + vv.y;
        vv = unpack2(add2(aH0A, aH1A)); const float sHA = vv.x + vv.y;
        vv = unpack2(add2(aL0B, aL1B)); const float sLB = vv.x + vv.y;
        vv = unpack2(add2(aH0B, aH1B)); const float sHB = vv.x + vv.y;
        pex[0][w][l] = pack2(sLA, sHA);
        pex[1][w][l] = pack2(sLB, sHB);
        __syncthreads();

        // ---- combine OWN batch only (b = 2*blk + w) ----
        float2 s = unpack2(add2(pex[w][0][l], pex[w][1][l]));
        const float hL = s.x + fmaf(e2, wih0L, fmaf(sig, wih1L, bbL));
        const float hH = s.y + fmaf(e2, wih0H, fmaf(sig, wih1H, bbH));
        hb[w][l]      = hL;
        hb[w][l + 32] = hH;

        // sigma for own batch: one butterfly + one softplus
        float d = fmaf(fcL, hL, fcH * hH);
#pragma unroll
        for (int o = 16; o; o >>= 1) d += __shfl_xor_sync(FULLMASK, d, o);
        sig = softplus_fast(d + fcb) + EPSV;
        if (l == 0) op[t] = sig;

        __syncthreads();
    }
}

// --------------------------------------------------------------------------
extern "C" void kernel_launch(void* const* d_in, const int* in_sizes, int n_in,
                              void* d_out, int out_size) {
    const float* res  = (const float*)d_in[0];
    const float* Wih  = (const float*)d_in[1];
    const float* bih  = (const float*)d_in[2];
    const float* Whh  = (const float*)d_in[3];
    const float* bhh  = (const float*)d_in[4];
    const float* fcw  = (const float*)d_in[5];
    const float* fcb  = (const float*)d_in[6];
    float* out = (float*)d_out;

    var_kernel<<<BB, 256>>>(res, out);
    rnn_kernel<<<BB / 2, 64>>>(res, Wih, bih, Whh, bhh, fcw, fcb, out);
}